// round 14
// baseline (speedup 1.0000x reference)
#include <cuda_runtime.h>
#include <math_constants.h>
#include <stdint.h>

// Problem constants
#define B_   64
#define L_   1024
#define D_   64
#define BQ   32          // q rows per CTA
#define CH   64          // keys per chunk
#define NCH  (L_ / CH)   // 16
#define THREADS 512

#define SP   1028        // sS pitch (mod 32 == 4 -> conflict-free frag loads)
#define KP   68          // K-phase pitch inside buf (mod 32 == 4)
#define VP   72          // V-phase pitch inside buf (mod 32 == 8)
#define BUFSZ (CH * VP)  // 4608 floats per buffer

// smem (floats): sS[32][1028] | buf[2][BUFSZ] | sSum[32] | sInv[32]
#define OFF_BUF (BQ * SP)
#define OFF_SUM (OFF_BUF + 2 * BUFSZ)
#define OFF_INV (OFF_SUM + 32)
#define SMEM_FLOATS (OFF_INV + 32)      // 42176 floats = 168704 B -> 1 CTA/SM

// 0 = mask is 1 byte/element, 1 = mask is 4 bytes/element (int32 or float32)
__device__ int g_mask_w4;

__global__ void detect_mask_kernel(const unsigned* m)
{
    __shared__ int ok;
    if (threadIdx.x == 0) ok = 1;
    __syncthreads();
    #pragma unroll
    for (int p = 0; p < 16; p++) {
        unsigned v = m[threadIdx.x + p * 256];
        if (!(v == 0u || v == 1u || v == 0x3F800000u)) ok = 0;
    }
    __syncthreads();
    if (threadIdx.x == 0) g_mask_w4 = ok;
}

__device__ __forceinline__ float tf32r(float x) {
    uint32_t u;
    asm("cvt.rna.tf32.f32 %0, %1;" : "=r"(u) : "f"(x));
    return __uint_as_float(u);
}

__device__ __forceinline__ void cp_async16(uint32_t saddr, const void* gaddr) {
    asm volatile("cp.async.cg.shared.global [%0], [%1], 16;" :: "r"(saddr), "l"(gaddr));
}
__device__ __forceinline__ void cp_commit() { asm volatile("cp.async.commit_group;"); }
template<int N> __device__ __forceinline__ void cp_wait() {
    asm volatile("cp.async.wait_group %0;" :: "n"(N));
}

#define MMA_TF32(c, A0, A1, A2, A3, Bb0, Bb1)                                   \
    asm volatile(                                                               \
        "mma.sync.aligned.m16n8k8.row.col.f32.tf32.tf32.f32 "                   \
        "{%0,%1,%2,%3}, {%4,%5,%6,%7}, {%8,%9}, {%0,%1,%2,%3};"                 \
        : "+f"((c)[0]), "+f"((c)[1]), "+f"((c)[2]), "+f"((c)[3])                \
        : "r"(__float_as_uint(A0)), "r"(__float_as_uint(A1)),                   \
          "r"(__float_as_uint(A2)), "r"(__float_as_uint(A3)),                   \
          "r"(__float_as_uint(Bb0)), "r"(__float_as_uint(Bb1)))

__global__ __launch_bounds__(THREADS, 1)
void attn_tf32_kernel(const float* __restrict__ q,
                      const float* __restrict__ k,
                      const float* __restrict__ v,
                      const void* __restrict__ maskp,
                      float* __restrict__ outO,
                      float* __restrict__ outA)
{
    extern __shared__ float smem[];
    float* sS   = smem;
    float* buf  = smem + OFF_BUF;
    float* sSum = smem + OFF_SUM;
    float* sInv = smem + OFF_INV;

    const int b   = blockIdx.y;
    const int q0  = blockIdx.x * BQ;
    const int t    = threadIdx.x;
    const int warp = t >> 5;
    const int lane = t & 31;
    const int gid  = lane >> 2;   // groupID 0..7
    const int tig  = lane & 3;    // thread-in-group 0..3

    const int mw = warp & 1;      // m-tile 0/1 (rows mw*16..+15)
    const int nw = warp >> 1;     // n-tile 0..7
    const int r0 = mw * 16;
    const int n0 = nw * 8;        // keys within chunk (phase 1) / d-cols (phase 2)

    const int mask_w4 = g_mask_w4;

    const float* qb = q + ((size_t)b * L_ + q0) * D_;
    const float* kb = k + (size_t)b * L_ * D_;
    const float* vb = v + (size_t)b * L_ * D_;
    const size_t mbase = ((size_t)b * L_ + q0) * (size_t)L_;
    const unsigned char* mb8 = (const unsigned char*)maskp + mbase;
    const unsigned*      mb4 = (const unsigned*)maskp + mbase;
    float* oOb = outO + ((size_t)b * L_ + q0) * D_;
    float* oAb = outA + ((size_t)b * L_ + q0) * (size_t)L_;

    if (t < 32) sSum[t] = 0.f;

    // ---- prefetch K chunk 0 (64 keys x 64 d, pitch KP) ----
    #pragma unroll
    for (int p = 0; p < 2; p++) {
        int idx = t + p * THREADS;                   // 1024 float4
        int r = idx >> 4, c4 = idx & 15;
        uint32_t sa = (uint32_t)__cvta_generic_to_shared(&buf[r * KP + c4 * 4]);
        cp_async16(sa, &kb[r * 64 + c4 * 4]);
    }
    cp_commit();

    // ---- Q fragments -> registers (scale 1/8, hi/lo split), loaded ONCE ----
    // qA[ks][i] = {hi, lo}; i: 0=(r0+gid, k0+tig) 1=(r0+8+gid, k0+tig)
    //                          2=(r0+gid, k0+4+tig) 3=(r0+8+gid, k0+4+tig)
    float2 qA[8][4];
    {
        const float* qra = qb + (r0 + gid) * D_;
        const float* qrb = qb + (r0 + 8 + gid) * D_;
        #pragma unroll
        for (int ks = 0; ks < 8; ks++) {
            const int k0 = ks * 8;
            float x0 = qra[k0 + tig]     * 0.125f;
            float x1 = qrb[k0 + tig]     * 0.125f;
            float x2 = qra[k0 + 4 + tig] * 0.125f;
            float x3 = qrb[k0 + 4 + tig] * 0.125f;
            float h0 = tf32r(x0), h1 = tf32r(x1), h2 = tf32r(x2), h3 = tf32r(x3);
            qA[ks][0] = make_float2(h0, tf32r(x0 - h0));
            qA[ks][1] = make_float2(h1, tf32r(x1 - h1));
            qA[ks][2] = make_float2(h2, tf32r(x2 - h2));
            qA[ks][3] = make_float2(h3, tf32r(x3 - h3));
        }
    }

    // ================= Phase 1: sS = exp(mask(QK^T / 8)) + row sums =================
    for (int c = 0; c < NCH; c++) {
        const int cur = c & 1, nxt = cur ^ 1;
        if (c + 1 < NCH) {
            #pragma unroll
            for (int p = 0; p < 2; p++) {
                int idx = t + p * THREADS;
                int r = idx >> 4, c4 = idx & 15;
                uint32_t sa = (uint32_t)__cvta_generic_to_shared(
                    &buf[nxt * BUFSZ + r * KP + c4 * 4]);
                cp_async16(sa, &kb[((c + 1) * CH + r) * 64 + c4 * 4]);
            }
            cp_commit();
            cp_wait<1>();
        } else {
            cp_wait<0>();
        }
        __syncthreads();

        const float* kr0 = &buf[cur * BUFSZ + (n0 + gid) * KP + tig];
        float acc[4] = {0.f, 0.f, 0.f, 0.f};

        #pragma unroll
        for (int ks = 0; ks < 8; ks++) {
            float br0 = kr0[ks * 8];
            float br1 = kr0[ks * 8 + 4];
            float bh0 = tf32r(br0), bl0 = tf32r(br0 - bh0);
            float bh1 = tf32r(br1), bl1 = tf32r(br1 - bh1);
            MMA_TF32(acc, qA[ks][0].x, qA[ks][1].x, qA[ks][2].x, qA[ks][3].x, bh0, bh1);
            MMA_TF32(acc, qA[ks][0].y, qA[ks][1].y, qA[ks][2].y, qA[ks][3].y, bh0, bh1);
            MMA_TF32(acc, qA[ks][0].x, qA[ks][1].x, qA[ks][2].x, qA[ks][3].x, bl0, bl1);
        }

        // epilogue: mask -> exp -> store sS tf32-rounded (unnormalized), row sums
        {
            float s_lo = 0.f, s_hi = 0.f;
            float st[4];
            #pragma unroll
            for (int e = 0; e < 4; e++) {
                int row = r0 + gid + (e >> 1) * 8;
                int g   = c * CH + n0 + 2 * tig + (e & 1);
                unsigned midx = (unsigned)row * L_ + (unsigned)g;
                bool msk = mask_w4 ? (mb4[midx] != 0u) : (mb8[midx] != 0);
                float ex = msk ? 0.f : __expf(acc[e]);
                st[e] = tf32r(ex);
                if (e < 2) s_lo += ex; else s_hi += ex;
            }
            int colb = c * CH + n0 + 2 * tig;
            *(float2*)&sS[(r0 + gid)     * SP + colb] = make_float2(st[0], st[1]);
            *(float2*)&sS[(r0 + 8 + gid) * SP + colb] = make_float2(st[2], st[3]);

            s_lo += __shfl_xor_sync(0xFFFFFFFFu, s_lo, 1);
            s_lo += __shfl_xor_sync(0xFFFFFFFFu, s_lo, 2);
            s_hi += __shfl_xor_sync(0xFFFFFFFFu, s_hi, 1);
            s_hi += __shfl_xor_sync(0xFFFFFFFFu, s_hi, 2);
            if (tig == 0) {
                atomicAdd(&sSum[r0 + gid],     s_lo);
                atomicAdd(&sSum[r0 + 8 + gid], s_hi);
            }
        }
        __syncthreads();
    }

    // row reciprocals
    if (t < 32) sInv[t] = 1.f / sSum[t];

    // ---- prefetch V chunk 0 (pitch VP); overlaps with attn write below ----
    #pragma unroll
    for (int p = 0; p < 2; p++) {
        int idx = t + p * THREADS;
        int r = idx >> 4, c4 = idx & 15;
        uint32_t sa = (uint32_t)__cvta_generic_to_shared(&buf[r * VP + c4 * 4]);
        cp_async16(sa, &vb[r * 64 + c4 * 4]);
    }
    cp_commit();
    __syncthreads();   // sInv visible

    // ---- write normalized attn (sS stays unnormalized for PV) ----
    #pragma unroll
    for (int rr = 0; rr < 2; rr++) {
        int row = warp * 2 + rr;
        float inv = sInv[row];
        const float* srow = &sS[row * SP];
        float* arow = &oAb[(size_t)row * L_];
        for (int j = lane; j < L_; j += 32)
            arow[j] = srow[j] * inv;
    }

    // ================= Phase 2: O = P @ V (single-pass tf32, m16n8) =================
    float acc2[4] = {0.f, 0.f, 0.f, 0.f};
    const float* sa0 = &sS[(r0 + gid) * SP + tig];       // row r0+gid
    const float* sa1 = &sS[(r0 + 8 + gid) * SP + tig];   // row r0+8+gid

    for (int c = 0; c < NCH; c++) {
        const int cur = c & 1, nxt = cur ^ 1;
        if (c + 1 < NCH) {
            #pragma unroll
            for (int p = 0; p < 2; p++) {
                int idx = t + p * THREADS;
                int r = idx >> 4, c4 = idx & 15;
                uint32_t sa = (uint32_t)__cvta_generic_to_shared(
                    &buf[nxt * BUFSZ + r * VP + c4 * 4]);
                cp_async16(sa, &vb[((c + 1) * CH + r) * 64 + c4 * 4]);
            }
            cp_commit();
            cp_wait<1>();
        } else {
            cp_wait<0>();
        }
        __syncthreads();

        const float* vbase = &buf[cur * BUFSZ + tig * VP + n0 + gid];

        #pragma unroll
        for (int ks = 0; ks < 8; ks++) {
            const int kc = ks * 8;                  // key offset within chunk
            const int kg = c * CH + kc;             // global key (sS col)
            float a0 = sa0[kg];                     // pre-rounded tf32
            float a1 = sa1[kg];
            float a2 = sa0[kg + 4];
            float a3 = sa1[kg + 4];
            float br0 = vbase[kc * VP];
            float br1 = vbase[(kc + 4) * VP];
            float bh0 = tf32r(br0), bh1 = tf32r(br1);
            MMA_TF32(acc2, a0, a1, a2, a3, bh0, bh1);
        }
        __syncthreads();
    }

    // ---- scale by 1/sum, write O (each warp owns its m16n8 tile; no reduce) ----
    #pragma unroll
    for (int e = 0; e < 4; e++) {
        int row = r0 + gid + (e >> 1) * 8;
        int col = n0 + 2 * tig + (e & 1);
        oOb[(size_t)row * D_ + col] = acc2[e] * sInv[row];
    }
}

extern "C" void kernel_launch(void* const* d_in, const int* in_sizes, int n_in,
                              void* d_out, int out_size)
{
    const float* q = (const float*)d_in[0];
    const float* k = (const float*)d_in[1];
    const float* v = (const float*)d_in[2];
    const void*  mask = d_in[3];

    float* outO = (float*)d_out;                               // (B, Lq, D)
    float* outA = outO + (size_t)B_ * L_ * D_;                 // (B, Lq, Lk)

    const int smem_bytes = SMEM_FLOATS * (int)sizeof(float);   // 168704 B
    cudaFuncSetAttribute(attn_tf32_kernel,
                         cudaFuncAttributeMaxDynamicSharedMemorySize, smem_bytes);

    detect_mask_kernel<<<1, 256>>>((const unsigned*)mask);

    dim3 grid(L_ / BQ, B_);   // (32, 64)
    attn_tf32_kernel<<<grid, THREADS, smem_bytes>>>(q, k, v, mask, outO, outA);
}